// round 14
// baseline (speedup 1.0000x reference)
#include <cuda_runtime.h>
#include <cuda_fp16.h>
#include <math.h>
#include <cstdint>

#define N_NODES 50000
#define N_EDGES 800000
#define FEA     128      // HEADS*HID
#define HEADS   8
#define NCLS    10
#define NEG     0.2f
#define PADH    136      // smem row stride in halves; conflict-free LDSM phases

#define SCAN_BLK 1024
#define NPART ((N_NODES + SCAN_BLK - 1) / SCAN_BLK)   // 49

// ---------------- scratch (device globals: zero-initialized at module load) --
__device__ __half g_feat16[N_NODES * FEA];
__device__ __half g_hA[N_NODES * FEA];
__device__ __half g_hB[N_NODES * FEA];
__device__ __half g_Whi[4 * FEA * FEA];   // pre-split W, transposed [n][k]
__device__ __half g_Wlo[4 * FEA * FEA];
__device__ float g_el[N_NODES * HEADS];
__device__ float g_er[N_NODES * HEADS];
__device__ float g_feat5[N_NODES * NCLS];
__device__ float g_el5[N_NODES];
__device__ float g_er5[N_NODES];
__device__ int   g_cnt[N_NODES];          // zero at entry (re-zeroed at end)
__device__ int   g_off[N_NODES + 1];
__device__ int   g_part[NPART];
__device__ int   g_rank[N_EDGES];
__device__ int   g_ssrc[N_EDGES];

// ---------------- CSR build --------------------------------------------------
// g_cnt is zero on entry (module-load init + end-of-pipeline rezero below).
__global__ void count_rank_kernel(const int* __restrict__ dst) {
    int i = (blockIdx.x * blockDim.x + threadIdx.x) * 4;
    if (i < N_EDGES) {
        int4 d = *(const int4*)(dst + i);
        g_rank[i]     = atomicAdd(&g_cnt[d.x], 1);
        g_rank[i + 1] = atomicAdd(&g_cnt[d.y], 1);
        g_rank[i + 2] = atomicAdd(&g_cnt[d.z], 1);
        g_rank[i + 3] = atomicAdd(&g_cnt[d.w], 1);
    }
}

__global__ void scan1_kernel() {
    __shared__ int wsum[32];
    int tid = threadIdx.x, lane = tid & 31, wid = tid >> 5;
    int i = blockIdx.x * SCAN_BLK + tid;
    int v = (i < N_NODES) ? g_cnt[i] : 0;
    int x = v;
    #pragma unroll
    for (int d = 1; d < 32; d <<= 1) {
        int t = __shfl_up_sync(0xffffffffu, x, d);
        if (lane >= d) x += t;
    }
    if (lane == 31) wsum[wid] = x;
    __syncthreads();
    if (wid == 0) {
        int s = wsum[lane];
        #pragma unroll
        for (int d = 1; d < 32; d <<= 1) {
            int t = __shfl_up_sync(0xffffffffu, s, d);
            if (lane >= d) s += t;
        }
        wsum[lane] = s;
    }
    __syncthreads();
    int pre = (wid > 0) ? wsum[wid - 1] : 0;
    int incl = x + pre;
    if (i < N_NODES) g_off[i] = incl - v;       // block-local exclusive
    if (tid == SCAN_BLK - 1) g_part[blockIdx.x] = incl;
}

__global__ void scan3_kernel() {
    int i = blockIdx.x * blockDim.x + threadIdx.x;
    int part = (blockIdx.x * blockDim.x) / SCAN_BLK;
    int base = 0;
    for (int p = 0; p < part; p++) base += g_part[p];
    if (i < N_NODES) {
        g_off[i] += base;
        if (i == N_NODES - 1) g_off[N_NODES] = g_off[i] + g_cnt[i];
    }
}

__global__ void scatter2_kernel(const int* __restrict__ src, const int* __restrict__ dst) {
    int i = (blockIdx.x * blockDim.x + threadIdx.x) * 4;
    if (i < N_EDGES) {
        int4 s = *(const int4*)(src + i);
        int4 d = *(const int4*)(dst + i);
        int4 r = *(const int4*)(g_rank + i);
        g_ssrc[g_off[d.x] + r.x] = s.x;
        g_ssrc[g_off[d.y] + r.y] = s.y;
        g_ssrc[g_off[d.z] + r.z] = s.z;
        g_ssrc[g_off[d.w] + r.w] = s.w;
    }
}

// rezero g_cnt for the next graph replay (off critical path)
__global__ void rezero_kernel() {
    int i = blockIdx.x * blockDim.x + threadIdx.x;
    if (i < N_NODES) g_cnt[i] = 0;
}

// ---------------- W pre-split: fp32 [k][n] -> hi/lo fp16 transposed [n][k] ----
__global__ void wsplit_kernel(const float* __restrict__ W0, const float* __restrict__ W1,
                              const float* __restrict__ W2, const float* __restrict__ W3) {
    int layer = blockIdx.y;
    const float* W = (layer == 0) ? W0 : (layer == 1) ? W1 : (layer == 2) ? W2 : W3;
    int i = blockIdx.x * blockDim.x + threadIdx.x;   // 16384
    int k = i >> 7, n = i & 127;
    float v = W[i];
    __half hi = __float2half_rn(v);
    __half lo = __float2half_rn(v - __half2float(hi));
    g_Whi[layer * FEA * FEA + n * 128 + k] = hi;
    g_Wlo[layer * FEA * FEA + n * 128 + k] = lo;
}

// ---------------- fp16 tensor-core GEMM + fused el/er ------------------------
__device__ __forceinline__ void mma_f16(float* d, const uint32_t* a, const uint32_t* b) {
    asm volatile(
        "mma.sync.aligned.m16n8k16.row.col.f32.f16.f16.f32 "
        "{%0,%1,%2,%3}, {%4,%5,%6,%7}, {%8,%9}, {%0,%1,%2,%3};"
        : "+f"(d[0]), "+f"(d[1]), "+f"(d[2]), "+f"(d[3])
        : "r"(a[0]), "r"(a[1]), "r"(a[2]), "r"(a[3]), "r"(b[0]), "r"(b[1]));
}

__device__ __forceinline__ void ldsm4(uint32_t* r, uint32_t a) {
    asm volatile("ldmatrix.sync.aligned.m8n8.x4.shared.b16 {%0,%1,%2,%3}, [%4];"
        : "=r"(r[0]), "=r"(r[1]), "=r"(r[2]), "=r"(r[3]) : "r"(a));
}

__device__ __forceinline__ uint4 ld8h(const float* p) {
    float4 v0 = *(const float4*)p;
    float4 v1 = *(const float4*)(p + 4);
    uint4 r;
    *(__half2*)&r.x = __floats2half2_rn(v0.x, v0.y);
    *(__half2*)&r.y = __floats2half2_rn(v0.z, v0.w);
    *(__half2*)&r.z = __floats2half2_rn(v1.x, v1.y);
    *(__half2*)&r.w = __floats2half2_rn(v1.z, v1.w);
    return r;
}
__device__ __forceinline__ uint4 ld8h(const __half* p) { return *(const uint4*)p; }

__device__ __forceinline__ float qreduce(float v) {   // sum over quad
    v += __shfl_xor_sync(0xffffffffu, v, 1);
    v += __shfl_xor_sync(0xffffffffu, v, 2);
    return v;
}

// 128 rows x 128 cols per block, 256 threads (8 warps, 2m x 4n), warp tile 64x32.
template <typename TIN>
__global__ __launch_bounds__(256, 2)
void gemm_fp16(const TIN* __restrict__ hin, int layer,
               __half* __restrict__ feat16,
               const float* __restrict__ al, const float* __restrict__ ar) {
    extern __shared__ __half smh[];
    __half* As = smh;                 // [128][PADH]
    __half* Bh = As + 128 * PADH;     // [128][PADH]
    __half* Bl = Bh + 128 * PADH;
    int tid = threadIdx.x;
    int row0 = blockIdx.x * 128;
    const __half* Whi = g_Whi + layer * FEA * FEA;
    const __half* Wlo = g_Wlo + layer * FEA * FEA;

    #pragma unroll
    for (int it = 0; it < 8; it++) {
        int idx = tid + it * 256;            // 0..2047
        int r = idx >> 4, c8 = (idx & 15) * 8;
        int gr = row0 + r;
        uint4 v = make_uint4(0, 0, 0, 0);
        if (gr < N_NODES) v = ld8h(&hin[(size_t)gr * 128 + c8]);
        *(uint4*)&As[r * PADH + c8] = v;
    }
    #pragma unroll
    for (int it = 0; it < 8; it++) {
        int idx = tid + it * 256;
        int n = idx >> 4, c8 = (idx & 15) * 8;
        *(uint4*)&Bh[n * PADH + c8] = *(const uint4*)&Whi[n * 128 + c8];
        *(uint4*)&Bl[n * PADH + c8] = *(const uint4*)&Wlo[n * 128 + c8];
    }
    __syncthreads();

    int warp = tid >> 5, lane = tid & 31;
    int wm = warp & 1, wn = warp >> 1;       // 2 x 4 warp grid
    int m0 = wm * 64, n0 = wn * 32;
    int g = lane >> 2, t = lane & 3;

    uint32_t sA  = (uint32_t)__cvta_generic_to_shared(As);
    uint32_t sBh = (uint32_t)__cvta_generic_to_shared(Bh);
    uint32_t sBl = (uint32_t)__cvta_generic_to_shared(Bl);
    int aRow = lane & 15;
    int aCol8 = (lane >= 16) ? 8 : 0;
    uint32_t aBase[4];
    #pragma unroll
    for (int mt = 0; mt < 4; mt++)
        aBase[mt] = sA + (uint32_t)(((m0 + mt * 16 + aRow) * PADH + aCol8) * 2);
    int bRow = (lane & 7) + ((lane & 16) ? 8 : 0);
    int bCol8 = (lane & 8) ? 8 : 0;
    uint32_t bhBase[2], blBase[2];
    #pragma unroll
    for (int p = 0; p < 2; p++) {
        uint32_t off = (uint32_t)(((n0 + p * 16 + bRow) * PADH + bCol8) * 2);
        bhBase[p] = sBh + off;
        blBase[p] = sBl + off;
    }

    float acc[4][4][4];
    #pragma unroll
    for (int mt = 0; mt < 4; mt++)
        #pragma unroll
        for (int nt = 0; nt < 4; nt++)
            #pragma unroll
            for (int q = 0; q < 4; q++) acc[mt][nt][q] = 0.f;

    #pragma unroll
    for (int c = 0; c < 8; c++) {
        uint32_t koff = c * 32;
        uint32_t a[4][4], bh[2][4], bl[2][4];
        #pragma unroll
        for (int mt = 0; mt < 4; mt++) ldsm4(a[mt], aBase[mt] + koff);
        #pragma unroll
        for (int p = 0; p < 2; p++) { ldsm4(bh[p], bhBase[p] + koff); ldsm4(bl[p], blBase[p] + koff); }
        #pragma unroll
        for (int nt = 0; nt < 4; nt++) {
            int p = nt >> 1;
            const uint32_t* bhp = (nt & 1) ? &bh[p][2] : &bh[p][0];
            const uint32_t* blp = (nt & 1) ? &bl[p][2] : &bl[p][0];
            #pragma unroll
            for (int mt = 0; mt < 4; mt++) {
                mma_f16(acc[mt][nt], a[mt], bhp);
                mma_f16(acc[mt][nt], a[mt], blp);
            }
        }
    }

    float alv[4][2], arv[4][2];
    #pragma unroll
    for (int nt = 0; nt < 4; nt++) {
        int cc = n0 + nt * 8 + 2 * t;
        alv[nt][0] = al[cc];     alv[nt][1] = al[cc + 1];
        arv[nt][0] = ar[cc];     arv[nt][1] = ar[cc + 1];
    }

    #pragma unroll
    for (int mt = 0; mt < 4; mt++) {
        int rA = row0 + m0 + mt * 16 + g;
        int rB = rA + 8;
        float h0lA = 0, h1lA = 0, h0rA = 0, h1rA = 0;
        float h0lB = 0, h1lB = 0, h0rB = 0, h1rB = 0;
        #pragma unroll
        for (int nt = 0; nt < 4; nt++) {
            float pA = acc[mt][nt][0] * alv[nt][0] + acc[mt][nt][1] * alv[nt][1];
            float qA = acc[mt][nt][0] * arv[nt][0] + acc[mt][nt][1] * arv[nt][1];
            float pB = acc[mt][nt][2] * alv[nt][0] + acc[mt][nt][3] * alv[nt][1];
            float qB = acc[mt][nt][2] * arv[nt][0] + acc[mt][nt][3] * arv[nt][1];
            if (nt < 2) { h0lA += pA; h0rA += qA; h0lB += pB; h0rB += qB; }
            else        { h1lA += pA; h1rA += qA; h1lB += pB; h1rB += qB; }
        }
        h0lA = qreduce(h0lA); h1lA = qreduce(h1lA);
        h0rA = qreduce(h0rA); h1rA = qreduce(h1rA);
        h0lB = qreduce(h0lB); h1lB = qreduce(h1lB);
        h0rB = qreduce(h0rB); h1rB = qreduce(h1rB);
        if (t == 0) {
            if (rA < N_NODES) {
                g_el[rA * 8 + 2 * wn] = h0lA;  g_el[rA * 8 + 2 * wn + 1] = h1lA;
                g_er[rA * 8 + 2 * wn] = h0rA;  g_er[rA * 8 + 2 * wn + 1] = h1rA;
            }
            if (rB < N_NODES) {
                g_el[rB * 8 + 2 * wn] = h0lB;  g_el[rB * 8 + 2 * wn + 1] = h1lB;
                g_er[rB * 8 + 2 * wn] = h0rB;  g_er[rB * 8 + 2 * wn + 1] = h1rB;
            }
        }
        #pragma unroll
        for (int nt = 0; nt < 4; nt++) {
            int cc = n0 + nt * 8 + 2 * t;
            if (rA < N_NODES)
                *(__half2*)&feat16[(size_t)rA * 128 + cc] =
                    __floats2half2_rn(acc[mt][nt][0], acc[mt][nt][1]);
            if (rB < N_NODES)
                *(__half2*)&feat16[(size_t)rB * 128 + cc] =
                    __floats2half2_rn(acc[mt][nt][2], acc[mt][nt][3]);
        }
    }
}

__device__ __forceinline__ float leaky(float x) { return x > 0.f ? x : NEG * x; }

// ---------------- fused edge softmax + aggregate + ELU -----------------------
// Warp per node; the warp is split into two 16-lane halves, each handling one
// edge of a pair. Each lane loads 16B (uint4) of the 256B feature row, so a
// pair of edges costs 1 ssrc + 1 el + 1 feat LDG (vs 6 in the scalar form).
// head = (lane&15)>>1; parities merged at the end via shfl_xor(16).
__global__ void edge128_kernel(const __half* __restrict__ feat16,
                               __half* __restrict__ hout) {
    int node = (blockIdx.x * blockDim.x + threadIdx.x) >> 5;
    int lane = threadIdx.x & 31;
    if (node >= N_NODES) return;
    int beg = g_off[node], end = g_off[node + 1];
    int half = lane >> 4;        // edge parity within pair
    int sub  = lane & 15;        // feature group [sub*8, sub*8+8)
    int head = sub >> 1;
    float erh = g_er[node * 8 + head];

    float acc[8];
    #pragma unroll
    for (int q = 0; q < 8; q++) acc[q] = 0.f;
    float den = 0.f;

    int j = beg;
    // unrolled: 4 edges (2 pairs) per iteration
    for (; j + 4 <= end; j += 4) {
        int s0 = g_ssrc[j + half];
        int s1 = g_ssrc[j + 2 + half];
        float w0 = __expf(leaky(g_el[s0 * 8 + head] + erh));
        float w1 = __expf(leaky(g_el[s1 * 8 + head] + erh));
        uint4 f0 = *(const uint4*)(feat16 + (size_t)s0 * 128 + sub * 8);
        uint4 f1 = *(const uint4*)(feat16 + (size_t)s1 * 128 + sub * 8);
        {
            float2 p0 = __half22float2(*(__half2*)&f0.x);
            float2 p1 = __half22float2(*(__half2*)&f0.y);
            float2 p2 = __half22float2(*(__half2*)&f0.z);
            float2 p3 = __half22float2(*(__half2*)&f0.w);
            acc[0] += p0.x * w0; acc[1] += p0.y * w0;
            acc[2] += p1.x * w0; acc[3] += p1.y * w0;
            acc[4] += p2.x * w0; acc[5] += p2.y * w0;
            acc[6] += p3.x * w0; acc[7] += p3.y * w0;
        }
        {
            float2 p0 = __half22float2(*(__half2*)&f1.x);
            float2 p1 = __half22float2(*(__half2*)&f1.y);
            float2 p2 = __half22float2(*(__half2*)&f1.z);
            float2 p3 = __half22float2(*(__half2*)&f1.w);
            acc[0] += p0.x * w1; acc[1] += p0.y * w1;
            acc[2] += p1.x * w1; acc[3] += p1.y * w1;
            acc[4] += p2.x * w1; acc[5] += p2.y * w1;
            acc[6] += p3.x * w1; acc[7] += p3.y * w1;
        }
        den += w0 + w1;
    }
    // remainder pairs (predicated second half)
    for (; j < end; j += 2) {
        int jj = j + half;
        bool act = jj < end;
        int s = g_ssrc[act ? jj : (end - 1)];
        float w = act ? __expf(leaky(g_el[s * 8 + head] + erh)) : 0.f;
        uint4 f = *(const uint4*)(feat16 + (size_t)s * 128 + sub * 8);
        float2 p0 = __half22float2(*(__half2*)&f.x);
        float2 p1 = __half22float2(*(__half2*)&f.y);
        float2 p2 = __half22float2(*(__half2*)&f.z);
        float2 p3 = __half22float2(*(__half2*)&f.w);
        acc[0] += p0.x * w; acc[1] += p0.y * w;
        acc[2] += p1.x * w; acc[3] += p1.y * w;
        acc[4] += p2.x * w; acc[5] += p2.y * w;
        acc[6] += p3.x * w; acc[7] += p3.y * w;
        den += w;
    }

    // merge edge parities
    #pragma unroll
    for (int q = 0; q < 8; q++)
        acc[q] += __shfl_xor_sync(0xffffffffu, acc[q], 16);
    den += __shfl_xor_sync(0xffffffffu, den, 16);

    if (half == 0) {
        float inv = (den > 0.f) ? 1.f / den : 0.f;
        float o[8];
        #pragma unroll
        for (int q = 0; q < 8; q++) {
            float v = acc[q] * inv;
            o[q] = v > 0.f ? v : expm1f(v);
        }
        uint4 st;
        *(__half2*)&st.x = __floats2half2_rn(o[0], o[1]);
        *(__half2*)&st.y = __floats2half2_rn(o[2], o[3]);
        *(__half2*)&st.z = __floats2half2_rn(o[4], o[5]);
        *(__half2*)&st.w = __floats2half2_rn(o[6], o[7]);
        *(uint4*)(hout + (size_t)node * 128 + sub * 8) = st;
    }
}

// ---------------- final layer: GEMM (N,128)@(128,10) + el/er -----------------
__global__ void gemm10_kernel(const __half* __restrict__ hin,
                              const float* __restrict__ W,
                              const float* __restrict__ al,
                              const float* __restrict__ ar) {
    __shared__ float Ws[128 * NCLS];
    int tid = threadIdx.x;
    for (int i = tid; i < 128 * NCLS; i += blockDim.x) Ws[i] = W[i];
    __syncthreads();
    int node = (blockIdx.x * blockDim.x + tid) >> 5;
    int lane = tid & 31;
    if (node >= N_NODES) return;
    uint2 raw = *(const uint2*)&hin[(size_t)node * 128 + lane * 4];
    float2 f01 = __half22float2(*(__half2*)&raw.x);
    float2 f23 = __half22float2(*(__half2*)&raw.y);
    float acc[NCLS];
    int k0 = lane * 4;
    #pragma unroll
    for (int c = 0; c < NCLS; c++)
        acc[c] = f01.x * Ws[k0 * NCLS + c] + f01.y * Ws[(k0 + 1) * NCLS + c]
               + f23.x * Ws[(k0 + 2) * NCLS + c] + f23.y * Ws[(k0 + 3) * NCLS + c];
    #pragma unroll
    for (int c = 0; c < NCLS; c++) {
        #pragma unroll
        for (int d = 16; d >= 1; d >>= 1)
            acc[c] += __shfl_xor_sync(0xffffffffu, acc[c], d);
    }
    if (lane == 0) {
        float e_l = 0.f, e_r = 0.f;
        #pragma unroll
        for (int c = 0; c < NCLS; c++) {
            g_feat5[node * NCLS + c] = acc[c];
            e_l += acc[c] * al[c];
            e_r += acc[c] * ar[c];
        }
        g_el5[node] = e_l;
        g_er5[node] = e_r;
    }
}

__global__ void edge10_kernel(float* __restrict__ out) {
    int node = (blockIdx.x * blockDim.x + threadIdx.x) >> 5;
    int lane = threadIdx.x & 31;
    if (node >= N_NODES) return;
    int beg = g_off[node], end = g_off[node + 1];
    float ern = g_er5[node];
    float acc = 0.f, den = 0.f;
    for (int j = beg; j < end; j++) {
        int s = g_ssrc[j];
        float ex = __expf(leaky(g_el5[s] + ern));
        den += ex;
        if (lane < NCLS) acc += g_feat5[s * NCLS + lane] * ex;
    }
    if (lane < NCLS) out[node * NCLS + lane] = den > 0.f ? acc / den : 0.f;
}

// ---------------- launch -----------------------------------------------------
extern "C" void kernel_launch(void* const* d_in, const int* in_sizes, int n_in,
                              void* d_out, int out_size) {
    const float* h   = (const float*)d_in[0];
    const int*   src = (const int*)d_in[1];
    const int*   dst = (const int*)d_in[2];
    const float* W[5]; const float* al[5]; const float* ar[5];
    for (int i = 0; i < 5; i++) {
        W[i]  = (const float*)d_in[3 + 3 * i];
        al[i] = (const float*)d_in[4 + 3 * i];
        ar[i] = (const float*)d_in[5 + 3 * i];
    }

    __half *feat16, *hA, *hB;
    cudaGetSymbolAddress((void**)&feat16, g_feat16);
    cudaGetSymbolAddress((void**)&hA, g_hA);
    cudaGetSymbolAddress((void**)&hB, g_hB);

    const int smem_g = 3 * 128 * PADH * (int)sizeof(__half);   // 104448
    static bool s_init = false;
    static cudaStream_t s_csr;
    static cudaEvent_t ev_fork, ev_join, ev_done;
    if (!s_init) {
        cudaFuncSetAttribute(gemm_fp16<float>,
                             cudaFuncAttributeMaxDynamicSharedMemorySize, smem_g);
        cudaFuncSetAttribute(gemm_fp16<__half>,
                             cudaFuncAttributeMaxDynamicSharedMemorySize, smem_g);
        cudaStreamCreateWithFlags(&s_csr, cudaStreamNonBlocking);
        cudaEventCreateWithFlags(&ev_fork, cudaEventDisableTiming);
        cudaEventCreateWithFlags(&ev_join, cudaEventDisableTiming);
        cudaEventCreateWithFlags(&ev_done, cudaEventDisableTiming);
        s_init = true;
    }

    // ---- fork: CSR build on side stream, overlapped with W-split + layer-0 ----
    cudaEventRecord(ev_fork, 0);
    cudaStreamWaitEvent(s_csr, ev_fork, 0);
    count_rank_kernel<<<(N_EDGES / 4 + 255) / 256, 256, 0, s_csr>>>(dst);
    scan1_kernel<<<NPART, SCAN_BLK, 0, s_csr>>>();
    scan3_kernel<<<(N_NODES + 255) / 256, 256, 0, s_csr>>>();
    scatter2_kernel<<<(N_EDGES / 4 + 255) / 256, 256, 0, s_csr>>>(src, dst);
    cudaEventRecord(ev_join, s_csr);
    // rezero g_cnt for next replay — off the edge-0 critical path; joined at end
    rezero_kernel<<<(N_NODES + 255) / 256, 256, 0, s_csr>>>();
    cudaEventRecord(ev_done, s_csr);

    const int node_warp_grid = (N_NODES * 32 + 255) / 256;  // warp per node
    const int gemm_grid = (N_NODES + 127) / 128;            // 391

    // W pre-split (all 4 layers, one launch)
    {
        dim3 g(64, 4);
        wsplit_kernel<<<g, 256>>>(W[0], W[1], W[2], W[3]);
    }

    // layer 0 feature path (independent of CSR)
    gemm_fp16<float><<<gemm_grid, 256, smem_g>>>(h, 0, feat16, al[0], ar[0]);
    cudaStreamWaitEvent(0, ev_join, 0);   // join before first edge kernel
    edge128_kernel<<<node_warp_grid, 256>>>(feat16, hA);

    // layers 1-3
    gemm_fp16<__half><<<gemm_grid, 256, smem_g>>>(hA, 1, feat16, al[1], ar[1]);
    edge128_kernel<<<node_warp_grid, 256>>>(feat16, hB);
    gemm_fp16<__half><<<gemm_grid, 256, smem_g>>>(hB, 2, feat16, al[2], ar[2]);
    edge128_kernel<<<node_warp_grid, 256>>>(feat16, hA);
    gemm_fp16<__half><<<gemm_grid, 256, smem_g>>>(hA, 3, feat16, al[3], ar[3]);
    edge128_kernel<<<node_warp_grid, 256>>>(feat16, hB);

    // final projection + edge softmax over 10-dim class features
    gemm10_kernel<<<node_warp_grid, 256>>>(hB, W[4], al[4], ar[4]);
    cudaStreamWaitEvent(0, ev_done, 0);   // join rezero before last kernel
    edge10_kernel<<<node_warp_grid, 256>>>((float*)d_out);
}

// round 15
// speedup vs baseline: 1.0711x; 1.0711x over previous
#include <cuda_runtime.h>
#include <cuda_fp16.h>
#include <math.h>
#include <cstdint>

#define N_NODES 50000
#define N_EDGES 800000
#define FEA     128      // HEADS*HID
#define HEADS   8
#define NCLS    10
#define NEG     0.2f
#define PADH    136      // smem row stride in halves; conflict-free LDSM phases

#define SCAN_BLK 1024
#define NPART ((N_NODES + SCAN_BLK - 1) / SCAN_BLK)   // 49

// ---------------- scratch (device globals: zero-initialized at module load) --
__device__ __half g_feat16[N_NODES * FEA];
__device__ __half g_hA[N_NODES * FEA];
__device__ __half g_hB[N_NODES * FEA];
__device__ __half g_Whi[4 * FEA * FEA];   // pre-split W, transposed [n][k]
__device__ __half g_Wlo[4 * FEA * FEA];
__device__ float g_el[N_NODES * HEADS];
__device__ float g_er[N_NODES * HEADS];
__device__ float g_feat5[N_NODES * NCLS];
__device__ float g_el5[N_NODES];
__device__ float g_er5[N_NODES];
__device__ int   g_cnt[N_NODES];          // zero at entry (re-zeroed at end)
__device__ int   g_off[N_NODES + 1];
__device__ int   g_part[NPART];
__device__ int   g_rank[N_EDGES];
__device__ int   g_ssrc[N_EDGES];

// ---------------- CSR build --------------------------------------------------
// g_cnt is zero on entry (module-load init + end-of-pipeline rezero below).
__global__ void count_rank_kernel(const int* __restrict__ dst) {
    int i = (blockIdx.x * blockDim.x + threadIdx.x) * 4;
    if (i < N_EDGES) {
        int4 d = *(const int4*)(dst + i);
        g_rank[i]     = atomicAdd(&g_cnt[d.x], 1);
        g_rank[i + 1] = atomicAdd(&g_cnt[d.y], 1);
        g_rank[i + 2] = atomicAdd(&g_cnt[d.z], 1);
        g_rank[i + 3] = atomicAdd(&g_cnt[d.w], 1);
    }
}

__global__ void scan1_kernel() {
    __shared__ int wsum[32];
    int tid = threadIdx.x, lane = tid & 31, wid = tid >> 5;
    int i = blockIdx.x * SCAN_BLK + tid;
    int v = (i < N_NODES) ? g_cnt[i] : 0;
    int x = v;
    #pragma unroll
    for (int d = 1; d < 32; d <<= 1) {
        int t = __shfl_up_sync(0xffffffffu, x, d);
        if (lane >= d) x += t;
    }
    if (lane == 31) wsum[wid] = x;
    __syncthreads();
    if (wid == 0) {
        int s = wsum[lane];
        #pragma unroll
        for (int d = 1; d < 32; d <<= 1) {
            int t = __shfl_up_sync(0xffffffffu, s, d);
            if (lane >= d) s += t;
        }
        wsum[lane] = s;
    }
    __syncthreads();
    int pre = (wid > 0) ? wsum[wid - 1] : 0;
    int incl = x + pre;
    if (i < N_NODES) g_off[i] = incl - v;       // block-local exclusive
    if (tid == SCAN_BLK - 1) g_part[blockIdx.x] = incl;
}

__global__ void scan3_kernel() {
    int i = blockIdx.x * blockDim.x + threadIdx.x;
    int part = (blockIdx.x * blockDim.x) / SCAN_BLK;
    int base = 0;
    for (int p = 0; p < part; p++) base += g_part[p];
    if (i < N_NODES) {
        g_off[i] += base;
        if (i == N_NODES - 1) g_off[N_NODES] = g_off[i] + g_cnt[i];
    }
}

__global__ void scatter2_kernel(const int* __restrict__ src, const int* __restrict__ dst) {
    int i = (blockIdx.x * blockDim.x + threadIdx.x) * 4;
    if (i < N_EDGES) {
        int4 s = *(const int4*)(src + i);
        int4 d = *(const int4*)(dst + i);
        int4 r = *(const int4*)(g_rank + i);
        g_ssrc[g_off[d.x] + r.x] = s.x;
        g_ssrc[g_off[d.y] + r.y] = s.y;
        g_ssrc[g_off[d.z] + r.z] = s.z;
        g_ssrc[g_off[d.w] + r.w] = s.w;
    }
}

// rezero g_cnt for the next graph replay (off critical path)
__global__ void rezero_kernel() {
    int i = blockIdx.x * blockDim.x + threadIdx.x;
    if (i < N_NODES) g_cnt[i] = 0;
}

// ---------------- W pre-split: fp32 [k][n] -> hi/lo fp16 transposed [n][k] ----
__global__ void wsplit_kernel(const float* __restrict__ W0, const float* __restrict__ W1,
                              const float* __restrict__ W2, const float* __restrict__ W3) {
    int layer = blockIdx.y;
    const float* W = (layer == 0) ? W0 : (layer == 1) ? W1 : (layer == 2) ? W2 : W3;
    int i = blockIdx.x * blockDim.x + threadIdx.x;   // 16384
    int k = i >> 7, n = i & 127;
    float v = W[i];
    __half hi = __float2half_rn(v);
    __half lo = __float2half_rn(v - __half2float(hi));
    g_Whi[layer * FEA * FEA + n * 128 + k] = hi;
    g_Wlo[layer * FEA * FEA + n * 128 + k] = lo;
}

// ---------------- fp16 tensor-core GEMM + fused el/er ------------------------
__device__ __forceinline__ void mma_f16(float* d, const uint32_t* a, const uint32_t* b) {
    asm volatile(
        "mma.sync.aligned.m16n8k16.row.col.f32.f16.f16.f32 "
        "{%0,%1,%2,%3}, {%4,%5,%6,%7}, {%8,%9}, {%0,%1,%2,%3};"
        : "+f"(d[0]), "+f"(d[1]), "+f"(d[2]), "+f"(d[3])
        : "r"(a[0]), "r"(a[1]), "r"(a[2]), "r"(a[3]), "r"(b[0]), "r"(b[1]));
}

__device__ __forceinline__ void ldsm4(uint32_t* r, uint32_t a) {
    asm volatile("ldmatrix.sync.aligned.m8n8.x4.shared.b16 {%0,%1,%2,%3}, [%4];"
        : "=r"(r[0]), "=r"(r[1]), "=r"(r[2]), "=r"(r[3]) : "r"(a));
}

__device__ __forceinline__ uint4 ld8h(const float* p) {
    float4 v0 = *(const float4*)p;
    float4 v1 = *(const float4*)(p + 4);
    uint4 r;
    *(__half2*)&r.x = __floats2half2_rn(v0.x, v0.y);
    *(__half2*)&r.y = __floats2half2_rn(v0.z, v0.w);
    *(__half2*)&r.z = __floats2half2_rn(v1.x, v1.y);
    *(__half2*)&r.w = __floats2half2_rn(v1.z, v1.w);
    return r;
}
__device__ __forceinline__ uint4 ld8h(const __half* p) { return *(const uint4*)p; }

__device__ __forceinline__ float qreduce(float v) {   // sum over quad
    v += __shfl_xor_sync(0xffffffffu, v, 1);
    v += __shfl_xor_sync(0xffffffffu, v, 2);
    return v;
}

// 128 rows x 128 cols per block, 256 threads (8 warps, 2m x 4n), warp tile 64x32.
template <typename TIN>
__global__ __launch_bounds__(256, 2)
void gemm_fp16(const TIN* __restrict__ hin, int layer,
               __half* __restrict__ feat16,
               const float* __restrict__ al, const float* __restrict__ ar) {
    extern __shared__ __half smh[];
    __half* As = smh;                 // [128][PADH]
    __half* Bh = As + 128 * PADH;     // [128][PADH]
    __half* Bl = Bh + 128 * PADH;
    int tid = threadIdx.x;
    int row0 = blockIdx.x * 128;
    const __half* Whi = g_Whi + layer * FEA * FEA;
    const __half* Wlo = g_Wlo + layer * FEA * FEA;

    #pragma unroll
    for (int it = 0; it < 8; it++) {
        int idx = tid + it * 256;            // 0..2047
        int r = idx >> 4, c8 = (idx & 15) * 8;
        int gr = row0 + r;
        uint4 v = make_uint4(0, 0, 0, 0);
        if (gr < N_NODES) v = ld8h(&hin[(size_t)gr * 128 + c8]);
        *(uint4*)&As[r * PADH + c8] = v;
    }
    #pragma unroll
    for (int it = 0; it < 8; it++) {
        int idx = tid + it * 256;
        int n = idx >> 4, c8 = (idx & 15) * 8;
        *(uint4*)&Bh[n * PADH + c8] = *(const uint4*)&Whi[n * 128 + c8];
        *(uint4*)&Bl[n * PADH + c8] = *(const uint4*)&Wlo[n * 128 + c8];
    }
    __syncthreads();

    int warp = tid >> 5, lane = tid & 31;
    int wm = warp & 1, wn = warp >> 1;       // 2 x 4 warp grid
    int m0 = wm * 64, n0 = wn * 32;
    int g = lane >> 2, t = lane & 3;

    uint32_t sA  = (uint32_t)__cvta_generic_to_shared(As);
    uint32_t sBh = (uint32_t)__cvta_generic_to_shared(Bh);
    uint32_t sBl = (uint32_t)__cvta_generic_to_shared(Bl);
    int aRow = lane & 15;
    int aCol8 = (lane >= 16) ? 8 : 0;
    uint32_t aBase[4];
    #pragma unroll
    for (int mt = 0; mt < 4; mt++)
        aBase[mt] = sA + (uint32_t)(((m0 + mt * 16 + aRow) * PADH + aCol8) * 2);
    int bRow = (lane & 7) + ((lane & 16) ? 8 : 0);
    int bCol8 = (lane & 8) ? 8 : 0;
    uint32_t bhBase[2], blBase[2];
    #pragma unroll
    for (int p = 0; p < 2; p++) {
        uint32_t off = (uint32_t)(((n0 + p * 16 + bRow) * PADH + bCol8) * 2);
        bhBase[p] = sBh + off;
        blBase[p] = sBl + off;
    }

    float acc[4][4][4];
    #pragma unroll
    for (int mt = 0; mt < 4; mt++)
        #pragma unroll
        for (int nt = 0; nt < 4; nt++)
            #pragma unroll
            for (int q = 0; q < 4; q++) acc[mt][nt][q] = 0.f;

    #pragma unroll
    for (int c = 0; c < 8; c++) {
        uint32_t koff = c * 32;
        uint32_t a[4][4], bh[2][4], bl[2][4];
        #pragma unroll
        for (int mt = 0; mt < 4; mt++) ldsm4(a[mt], aBase[mt] + koff);
        #pragma unroll
        for (int p = 0; p < 2; p++) { ldsm4(bh[p], bhBase[p] + koff); ldsm4(bl[p], blBase[p] + koff); }
        #pragma unroll
        for (int nt = 0; nt < 4; nt++) {
            int p = nt >> 1;
            const uint32_t* bhp = (nt & 1) ? &bh[p][2] : &bh[p][0];
            const uint32_t* blp = (nt & 1) ? &bl[p][2] : &bl[p][0];
            #pragma unroll
            for (int mt = 0; mt < 4; mt++) {
                mma_f16(acc[mt][nt], a[mt], bhp);
                mma_f16(acc[mt][nt], a[mt], blp);
            }
        }
    }

    float alv[4][2], arv[4][2];
    #pragma unroll
    for (int nt = 0; nt < 4; nt++) {
        int cc = n0 + nt * 8 + 2 * t;
        alv[nt][0] = al[cc];     alv[nt][1] = al[cc + 1];
        arv[nt][0] = ar[cc];     arv[nt][1] = ar[cc + 1];
    }

    #pragma unroll
    for (int mt = 0; mt < 4; mt++) {
        int rA = row0 + m0 + mt * 16 + g;
        int rB = rA + 8;
        float h0lA = 0, h1lA = 0, h0rA = 0, h1rA = 0;
        float h0lB = 0, h1lB = 0, h0rB = 0, h1rB = 0;
        #pragma unroll
        for (int nt = 0; nt < 4; nt++) {
            float pA = acc[mt][nt][0] * alv[nt][0] + acc[mt][nt][1] * alv[nt][1];
            float qA = acc[mt][nt][0] * arv[nt][0] + acc[mt][nt][1] * arv[nt][1];
            float pB = acc[mt][nt][2] * alv[nt][0] + acc[mt][nt][3] * alv[nt][1];
            float qB = acc[mt][nt][2] * arv[nt][0] + acc[mt][nt][3] * arv[nt][1];
            if (nt < 2) { h0lA += pA; h0rA += qA; h0lB += pB; h0rB += qB; }
            else        { h1lA += pA; h1rA += qA; h1lB += pB; h1rB += qB; }
        }
        h0lA = qreduce(h0lA); h1lA = qreduce(h1lA);
        h0rA = qreduce(h0rA); h1rA = qreduce(h1rA);
        h0lB = qreduce(h0lB); h1lB = qreduce(h1lB);
        h0rB = qreduce(h0rB); h1rB = qreduce(h1rB);
        if (t == 0) {
            if (rA < N_NODES) {
                g_el[rA * 8 + 2 * wn] = h0lA;  g_el[rA * 8 + 2 * wn + 1] = h1lA;
                g_er[rA * 8 + 2 * wn] = h0rA;  g_er[rA * 8 + 2 * wn + 1] = h1rA;
            }
            if (rB < N_NODES) {
                g_el[rB * 8 + 2 * wn] = h0lB;  g_el[rB * 8 + 2 * wn + 1] = h1lB;
                g_er[rB * 8 + 2 * wn] = h0rB;  g_er[rB * 8 + 2 * wn + 1] = h1rB;
            }
        }
        #pragma unroll
        for (int nt = 0; nt < 4; nt++) {
            int cc = n0 + nt * 8 + 2 * t;
            if (rA < N_NODES)
                *(__half2*)&feat16[(size_t)rA * 128 + cc] =
                    __floats2half2_rn(acc[mt][nt][0], acc[mt][nt][1]);
            if (rB < N_NODES)
                *(__half2*)&feat16[(size_t)rB * 128 + cc] =
                    __floats2half2_rn(acc[mt][nt][2], acc[mt][nt][3]);
        }
    }
}

__device__ __forceinline__ float leaky(float x) { return x > 0.f ? x : NEG * x; }

// ---------------- fused edge softmax + aggregate + ELU (warp per node) -------
// Latency-bound gather: batch 8 independent edges per iteration (MLP=8).
__global__ void edge128_kernel(const __half* __restrict__ feat16,
                               __half* __restrict__ hout) {
    int node = (blockIdx.x * blockDim.x + threadIdx.x) >> 5;
    int lane = threadIdx.x & 31;
    if (node >= N_NODES) return;
    int beg = g_off[node], end = g_off[node + 1];
    int head = lane >> 2;
    float erh = g_er[node * 8 + head];

    float4 acc = make_float4(0.f, 0.f, 0.f, 0.f);
    float den = 0.f;
    int j = beg;
    for (; j + 8 <= end; j += 8) {
        int s[8];
        #pragma unroll
        for (int q = 0; q < 8; q++) s[q] = g_ssrc[j + q];
        float e[8];
        #pragma unroll
        for (int q = 0; q < 8; q++) e[q] = g_el[s[q] * 8 + head];
        uint2 r[8];
        #pragma unroll
        for (int q = 0; q < 8; q++)
            r[q] = *(const uint2*)(feat16 + (size_t)s[q] * 128 + lane * 4);
        #pragma unroll
        for (int q = 0; q < 8; q++) {
            float w = __expf(leaky(e[q] + erh));
            float2 a01 = __half22float2(*(__half2*)&r[q].x);
            float2 a23 = __half22float2(*(__half2*)&r[q].y);
            acc.x += a01.x * w; acc.y += a01.y * w;
            acc.z += a23.x * w; acc.w += a23.y * w;
            den += w;
        }
    }
    for (; j + 4 <= end; j += 4) {
        int s0 = g_ssrc[j], s1 = g_ssrc[j + 1], s2 = g_ssrc[j + 2], s3 = g_ssrc[j + 3];
        float w0 = __expf(leaky(g_el[s0 * 8 + head] + erh));
        float w1 = __expf(leaky(g_el[s1 * 8 + head] + erh));
        float w2 = __expf(leaky(g_el[s2 * 8 + head] + erh));
        float w3 = __expf(leaky(g_el[s3 * 8 + head] + erh));
        uint2 r0 = *(const uint2*)(feat16 + (size_t)s0 * 128 + lane * 4);
        uint2 r1 = *(const uint2*)(feat16 + (size_t)s1 * 128 + lane * 4);
        uint2 r2 = *(const uint2*)(feat16 + (size_t)s2 * 128 + lane * 4);
        uint2 r3 = *(const uint2*)(feat16 + (size_t)s3 * 128 + lane * 4);
        {
            float2 a01 = __half22float2(*(__half2*)&r0.x);
            float2 a23 = __half22float2(*(__half2*)&r0.y);
            acc.x += a01.x * w0; acc.y += a01.y * w0;
            acc.z += a23.x * w0; acc.w += a23.y * w0;
        }
        {
            float2 a01 = __half22float2(*(__half2*)&r1.x);
            float2 a23 = __half22float2(*(__half2*)&r1.y);
            acc.x += a01.x * w1; acc.y += a01.y * w1;
            acc.z += a23.x * w1; acc.w += a23.y * w1;
        }
        {
            float2 a01 = __half22float2(*(__half2*)&r2.x);
            float2 a23 = __half22float2(*(__half2*)&r2.y);
            acc.x += a01.x * w2; acc.y += a01.y * w2;
            acc.z += a23.x * w2; acc.w += a23.y * w2;
        }
        {
            float2 a01 = __half22float2(*(__half2*)&r3.x);
            float2 a23 = __half22float2(*(__half2*)&r3.y);
            acc.x += a01.x * w3; acc.y += a01.y * w3;
            acc.z += a23.x * w3; acc.w += a23.y * w3;
        }
        den += w0 + w1 + w2 + w3;
    }
    for (; j < end; j++) {
        int s = g_ssrc[j];
        float w = __expf(leaky(g_el[s * 8 + head] + erh));
        uint2 r = *(const uint2*)(feat16 + (size_t)s * 128 + lane * 4);
        float2 a01 = __half22float2(*(__half2*)&r.x);
        float2 a23 = __half22float2(*(__half2*)&r.y);
        acc.x += a01.x * w; acc.y += a01.y * w;
        acc.z += a23.x * w; acc.w += a23.y * w;
        den += w;
    }

    float4 o = make_float4(0.f, 0.f, 0.f, 0.f);
    if (den > 0.f) {
        float inv = 1.f / den;
        o.x = acc.x * inv; o.y = acc.y * inv; o.z = acc.z * inv; o.w = acc.w * inv;
        o.x = o.x > 0.f ? o.x : expm1f(o.x);
        o.y = o.y > 0.f ? o.y : expm1f(o.y);
        o.z = o.z > 0.f ? o.z : expm1f(o.z);
        o.w = o.w > 0.f ? o.w : expm1f(o.w);
    }
    uint2 st;
    *(__half2*)&st.x = __floats2half2_rn(o.x, o.y);
    *(__half2*)&st.y = __floats2half2_rn(o.z, o.w);
    *(uint2*)(hout + (size_t)node * 128 + lane * 4) = st;
}

// ---------------- final layer: GEMM (N,128)@(128,10) + el/er -----------------
__global__ void gemm10_kernel(const __half* __restrict__ hin,
                              const float* __restrict__ W,
                              const float* __restrict__ al,
                              const float* __restrict__ ar) {
    __shared__ float Ws[128 * NCLS];
    int tid = threadIdx.x;
    for (int i = tid; i < 128 * NCLS; i += blockDim.x) Ws[i] = W[i];
    __syncthreads();
    int node = (blockIdx.x * blockDim.x + tid) >> 5;
    int lane = tid & 31;
    if (node >= N_NODES) return;
    uint2 raw = *(const uint2*)&hin[(size_t)node * 128 + lane * 4];
    float2 f01 = __half22float2(*(__half2*)&raw.x);
    float2 f23 = __half22float2(*(__half2*)&raw.y);
    float acc[NCLS];
    int k0 = lane * 4;
    #pragma unroll
    for (int c = 0; c < NCLS; c++)
        acc[c] = f01.x * Ws[k0 * NCLS + c] + f01.y * Ws[(k0 + 1) * NCLS + c]
               + f23.x * Ws[(k0 + 2) * NCLS + c] + f23.y * Ws[(k0 + 3) * NCLS + c];
    #pragma unroll
    for (int c = 0; c < NCLS; c++) {
        #pragma unroll
        for (int d = 16; d >= 1; d >>= 1)
            acc[c] += __shfl_xor_sync(0xffffffffu, acc[c], d);
    }
    if (lane == 0) {
        float e_l = 0.f, e_r = 0.f;
        #pragma unroll
        for (int c = 0; c < NCLS; c++) {
            g_feat5[node * NCLS + c] = acc[c];
            e_l += acc[c] * al[c];
            e_r += acc[c] * ar[c];
        }
        g_el5[node] = e_l;
        g_er5[node] = e_r;
    }
}

__global__ void edge10_kernel(float* __restrict__ out) {
    int node = (blockIdx.x * blockDim.x + threadIdx.x) >> 5;
    int lane = threadIdx.x & 31;
    if (node >= N_NODES) return;
    int beg = g_off[node], end = g_off[node + 1];
    float ern = g_er5[node];
    float acc = 0.f, den = 0.f;
    for (int j = beg; j < end; j++) {
        int s = g_ssrc[j];
        float ex = __expf(leaky(g_el5[s] + ern));
        den += ex;
        if (lane < NCLS) acc += g_feat5[s * NCLS + lane] * ex;
    }
    if (lane < NCLS) out[node * NCLS + lane] = den > 0.f ? acc / den : 0.f;
}

// ---------------- launch -----------------------------------------------------
extern "C" void kernel_launch(void* const* d_in, const int* in_sizes, int n_in,
                              void* d_out, int out_size) {
    const float* h   = (const float*)d_in[0];
    const int*   src = (const int*)d_in[1];
    const int*   dst = (const int*)d_in[2];
    const float* W[5]; const float* al[5]; const float* ar[5];
    for (int i = 0; i < 5; i++) {
        W[i]  = (const float*)d_in[3 + 3 * i];
        al[i] = (const float*)d_in[4 + 3 * i];
        ar[i] = (const float*)d_in[5 + 3 * i];
    }

    __half *feat16, *hA, *hB;
    cudaGetSymbolAddress((void**)&feat16, g_feat16);
    cudaGetSymbolAddress((void**)&hA, g_hA);
    cudaGetSymbolAddress((void**)&hB, g_hB);

    const int smem_g = 3 * 128 * PADH * (int)sizeof(__half);   // 104448
    static bool s_init = false;
    static cudaStream_t s_csr;
    static cudaEvent_t ev_fork, ev_join, ev_done;
    if (!s_init) {
        cudaFuncSetAttribute(gemm_fp16<float>,
                             cudaFuncAttributeMaxDynamicSharedMemorySize, smem_g);
        cudaFuncSetAttribute(gemm_fp16<__half>,
                             cudaFuncAttributeMaxDynamicSharedMemorySize, smem_g);
        cudaStreamCreateWithFlags(&s_csr, cudaStreamNonBlocking);
        cudaEventCreateWithFlags(&ev_fork, cudaEventDisableTiming);
        cudaEventCreateWithFlags(&ev_join, cudaEventDisableTiming);
        cudaEventCreateWithFlags(&ev_done, cudaEventDisableTiming);
        s_init = true;
    }

    // ---- fork: CSR build on side stream, overlapped with W-split + layer-0 ----
    cudaEventRecord(ev_fork, 0);
    cudaStreamWaitEvent(s_csr, ev_fork, 0);
    count_rank_kernel<<<(N_EDGES / 4 + 255) / 256, 256, 0, s_csr>>>(dst);
    scan1_kernel<<<NPART, SCAN_BLK, 0, s_csr>>>();
    scan3_kernel<<<(N_NODES + 255) / 256, 256, 0, s_csr>>>();
    scatter2_kernel<<<(N_EDGES / 4 + 255) / 256, 256, 0, s_csr>>>(src, dst);
    cudaEventRecord(ev_join, s_csr);
    // rezero g_cnt for next replay — off the edge-0 critical path; joined at end
    rezero_kernel<<<(N_NODES + 255) / 256, 256, 0, s_csr>>>();
    cudaEventRecord(ev_done, s_csr);

    const int node_warp_grid = (N_NODES * 32 + 255) / 256;  // warp per node
    const int gemm_grid = (N_NODES + 127) / 128;            // 391

    // W pre-split (all 4 layers, one launch)
    {
        dim3 g(64, 4);
        wsplit_kernel<<<g, 256>>>(W[0], W[1], W[2], W[3]);
    }

    // layer 0 feature path (independent of CSR)
    gemm_fp16<float><<<gemm_grid, 256, smem_g>>>(h, 0, feat16, al[0], ar[0]);
    cudaStreamWaitEvent(0, ev_join, 0);   // join before first edge kernel
    edge128_kernel<<<node_warp_grid, 256>>>(feat16, hA);

    // layers 1-3
    gemm_fp16<__half><<<gemm_grid, 256, smem_g>>>(hA, 1, feat16, al[1], ar[1]);
    edge128_kernel<<<node_warp_grid, 256>>>(feat16, hB);
    gemm_fp16<__half><<<gemm_grid, 256, smem_g>>>(hB, 2, feat16, al[2], ar[2]);
    edge128_kernel<<<node_warp_grid, 256>>>(feat16, hA);
    gemm_fp16<__half><<<gemm_grid, 256, smem_g>>>(hA, 3, feat16, al[3], ar[3]);
    edge128_kernel<<<node_warp_grid, 256>>>(feat16, hB);

    // final projection + edge softmax over 10-dim class features
    gemm10_kernel<<<node_warp_grid, 256>>>(hB, W[4], al[4], ar[4]);
    cudaStreamWaitEvent(0, ev_done, 0);   // join rezero before last kernel
    edge10_kernel<<<node_warp_grid, 256>>>((float*)d_out);
}

// round 16
// speedup vs baseline: 1.1450x; 1.0690x over previous
#include <cuda_runtime.h>
#include <cuda_fp16.h>
#include <math.h>
#include <cstdint>

#define N_NODES 50000
#define N_EDGES 800000
#define FEA     128      // HEADS*HID
#define HEADS   8
#define NCLS    10
#define NEG     0.2f
#define PADH    136      // smem row stride in halves; conflict-free LDSM phases

#define SCAN_BLK 1024
#define NPART ((N_NODES + SCAN_BLK - 1) / SCAN_BLK)   // 49

// ---------------- scratch (device globals: zero-initialized at module load) --
__device__ __half g_feat16[N_NODES * FEA];
__device__ __half g_hA[N_NODES * FEA];
__device__ __half g_hB[N_NODES * FEA];
__device__ __half g_W16[4 * FEA * FEA];   // fp16 W, transposed [n][k]
__device__ float g_el[N_NODES * HEADS];
__device__ float g_er[N_NODES * HEADS];
__device__ float g_feat5[N_NODES * NCLS];
__device__ float g_el5[N_NODES];
__device__ float g_er5[N_NODES];
__device__ int   g_cnt[N_NODES];          // zero at entry (re-zeroed at end)
__device__ int   g_off[N_NODES + 1];
__device__ int   g_part[NPART];
__device__ int   g_rank[N_EDGES];
__device__ int   g_ssrc[N_EDGES];

// ---------------- CSR build --------------------------------------------------
// g_cnt is zero on entry (module-load init + end-of-pipeline rezero below).
__global__ void count_rank_kernel(const int* __restrict__ dst) {
    int i = (blockIdx.x * blockDim.x + threadIdx.x) * 4;
    if (i < N_EDGES) {
        int4 d = *(const int4*)(dst + i);
        g_rank[i]     = atomicAdd(&g_cnt[d.x], 1);
        g_rank[i + 1] = atomicAdd(&g_cnt[d.y], 1);
        g_rank[i + 2] = atomicAdd(&g_cnt[d.z], 1);
        g_rank[i + 3] = atomicAdd(&g_cnt[d.w], 1);
    }
}

__global__ void scan1_kernel() {
    __shared__ int wsum[32];
    int tid = threadIdx.x, lane = tid & 31, wid = tid >> 5;
    int i = blockIdx.x * SCAN_BLK + tid;
    int v = (i < N_NODES) ? g_cnt[i] : 0;
    int x = v;
    #pragma unroll
    for (int d = 1; d < 32; d <<= 1) {
        int t = __shfl_up_sync(0xffffffffu, x, d);
        if (lane >= d) x += t;
    }
    if (lane == 31) wsum[wid] = x;
    __syncthreads();
    if (wid == 0) {
        int s = wsum[lane];
        #pragma unroll
        for (int d = 1; d < 32; d <<= 1) {
            int t = __shfl_up_sync(0xffffffffu, s, d);
            if (lane >= d) s += t;
        }
        wsum[lane] = s;
    }
    __syncthreads();
    int pre = (wid > 0) ? wsum[wid - 1] : 0;
    int incl = x + pre;
    if (i < N_NODES) g_off[i] = incl - v;       // block-local exclusive
    if (tid == SCAN_BLK - 1) g_part[blockIdx.x] = incl;
}

__global__ void scan3_kernel() {
    int i = blockIdx.x * blockDim.x + threadIdx.x;
    int part = (blockIdx.x * blockDim.x) / SCAN_BLK;
    int base = 0;
    for (int p = 0; p < part; p++) base += g_part[p];
    if (i < N_NODES) {
        g_off[i] += base;
        if (i == N_NODES - 1) g_off[N_NODES] = g_off[i] + g_cnt[i];
    }
}

__global__ void scatter2_kernel(const int* __restrict__ src, const int* __restrict__ dst) {
    int i = (blockIdx.x * blockDim.x + threadIdx.x) * 4;
    if (i < N_EDGES) {
        int4 s = *(const int4*)(src + i);
        int4 d = *(const int4*)(dst + i);
        int4 r = *(const int4*)(g_rank + i);
        g_ssrc[g_off[d.x] + r.x] = s.x;
        g_ssrc[g_off[d.y] + r.y] = s.y;
        g_ssrc[g_off[d.z] + r.z] = s.z;
        g_ssrc[g_off[d.w] + r.w] = s.w;
    }
}

// rezero g_cnt for the next graph replay (off critical path)
__global__ void rezero_kernel() {
    int i = blockIdx.x * blockDim.x + threadIdx.x;
    if (i < N_NODES) g_cnt[i] = 0;
}

// ---------------- W convert: fp32 [k][n] -> fp16 transposed [n][k] -----------
__global__ void wsplit_kernel(const float* __restrict__ W0, const float* __restrict__ W1,
                              const float* __restrict__ W2, const float* __restrict__ W3) {
    int layer = blockIdx.y;
    const float* W = (layer == 0) ? W0 : (layer == 1) ? W1 : (layer == 2) ? W2 : W3;
    int i = blockIdx.x * blockDim.x + threadIdx.x;   // 16384
    int k = i >> 7, n = i & 127;
    g_W16[layer * FEA * FEA + n * 128 + k] = __float2half_rn(W[i]);
}

// ---------------- fp16 tensor-core GEMM + fused el/er ------------------------
__device__ __forceinline__ void mma_f16(float* d, const uint32_t* a, const uint32_t* b) {
    asm volatile(
        "mma.sync.aligned.m16n8k16.row.col.f32.f16.f16.f32 "
        "{%0,%1,%2,%3}, {%4,%5,%6,%7}, {%8,%9}, {%0,%1,%2,%3};"
        : "+f"(d[0]), "+f"(d[1]), "+f"(d[2]), "+f"(d[3])
        : "r"(a[0]), "r"(a[1]), "r"(a[2]), "r"(a[3]), "r"(b[0]), "r"(b[1]));
}

__device__ __forceinline__ void ldsm4(uint32_t* r, uint32_t a) {
    asm volatile("ldmatrix.sync.aligned.m8n8.x4.shared.b16 {%0,%1,%2,%3}, [%4];"
        : "=r"(r[0]), "=r"(r[1]), "=r"(r[2]), "=r"(r[3]) : "r"(a));
}

__device__ __forceinline__ uint4 ld8h(const float* p) {
    float4 v0 = *(const float4*)p;
    float4 v1 = *(const float4*)(p + 4);
    uint4 r;
    *(__half2*)&r.x = __floats2half2_rn(v0.x, v0.y);
    *(__half2*)&r.y = __floats2half2_rn(v0.z, v0.w);
    *(__half2*)&r.z = __floats2half2_rn(v1.x, v1.y);
    *(__half2*)&r.w = __floats2half2_rn(v1.z, v1.w);
    return r;
}
__device__ __forceinline__ uint4 ld8h(const __half* p) { return *(const uint4*)p; }

__device__ __forceinline__ float qreduce(float v) {   // sum over quad
    v += __shfl_xor_sync(0xffffffffu, v, 1);
    v += __shfl_xor_sync(0xffffffffu, v, 2);
    return v;
}

// 128 rows x 128 cols per block, 256 threads (8 warps, 2m x 4n), warp tile 64x32.
template <typename TIN>
__global__ __launch_bounds__(256, 2)
void gemm_fp16(const TIN* __restrict__ hin, int layer,
               __half* __restrict__ feat16,
               const float* __restrict__ al, const float* __restrict__ ar) {
    extern __shared__ __half smh[];
    __half* As = smh;                 // [128][PADH]
    __half* Bs = As + 128 * PADH;     // [128][PADH]
    int tid = threadIdx.x;
    int row0 = blockIdx.x * 128;
    const __half* Wl = g_W16 + layer * FEA * FEA;

    #pragma unroll
    for (int it = 0; it < 8; it++) {
        int idx = tid + it * 256;            // 0..2047
        int r = idx >> 4, c8 = (idx & 15) * 8;
        int gr = row0 + r;
        uint4 v = make_uint4(0, 0, 0, 0);
        if (gr < N_NODES) v = ld8h(&hin[(size_t)gr * 128 + c8]);
        *(uint4*)&As[r * PADH + c8] = v;
    }
    #pragma unroll
    for (int it = 0; it < 8; it++) {
        int idx = tid + it * 256;
        int n = idx >> 4, c8 = (idx & 15) * 8;
        *(uint4*)&Bs[n * PADH + c8] = *(const uint4*)&Wl[n * 128 + c8];
    }
    __syncthreads();

    int warp = tid >> 5, lane = tid & 31;
    int wm = warp & 1, wn = warp >> 1;       // 2 x 4 warp grid
    int m0 = wm * 64, n0 = wn * 32;
    int g = lane >> 2, t = lane & 3;

    uint32_t sA = (uint32_t)__cvta_generic_to_shared(As);
    uint32_t sB = (uint32_t)__cvta_generic_to_shared(Bs);
    int aRow = lane & 15;
    int aCol8 = (lane >= 16) ? 8 : 0;
    uint32_t aBase[4];
    #pragma unroll
    for (int mt = 0; mt < 4; mt++)
        aBase[mt] = sA + (uint32_t)(((m0 + mt * 16 + aRow) * PADH + aCol8) * 2);
    int bRow = (lane & 7) + ((lane & 16) ? 8 : 0);
    int bCol8 = (lane & 8) ? 8 : 0;
    uint32_t bBase[2];
    #pragma unroll
    for (int p = 0; p < 2; p++)
        bBase[p] = sB + (uint32_t)(((n0 + p * 16 + bRow) * PADH + bCol8) * 2);

    float acc[4][4][4];
    #pragma unroll
    for (int mt = 0; mt < 4; mt++)
        #pragma unroll
        for (int nt = 0; nt < 4; nt++)
            #pragma unroll
            for (int q = 0; q < 4; q++) acc[mt][nt][q] = 0.f;

    #pragma unroll
    for (int c = 0; c < 8; c++) {
        uint32_t koff = c * 32;
        uint32_t a[4][4], bh[2][4];
        #pragma unroll
        for (int mt = 0; mt < 4; mt++) ldsm4(a[mt], aBase[mt] + koff);
        #pragma unroll
        for (int p = 0; p < 2; p++) ldsm4(bh[p], bBase[p] + koff);
        #pragma unroll
        for (int nt = 0; nt < 4; nt++) {
            int p = nt >> 1;
            const uint32_t* bhp = (nt & 1) ? &bh[p][2] : &bh[p][0];
            #pragma unroll
            for (int mt = 0; mt < 4; mt++)
                mma_f16(acc[mt][nt], a[mt], bhp);
        }
    }

    float alv[4][2], arv[4][2];
    #pragma unroll
    for (int nt = 0; nt < 4; nt++) {
        int cc = n0 + nt * 8 + 2 * t;
        alv[nt][0] = al[cc];     alv[nt][1] = al[cc + 1];
        arv[nt][0] = ar[cc];     arv[nt][1] = ar[cc + 1];
    }

    #pragma unroll
    for (int mt = 0; mt < 4; mt++) {
        int rA = row0 + m0 + mt * 16 + g;
        int rB = rA + 8;
        float h0lA = 0, h1lA = 0, h0rA = 0, h1rA = 0;
        float h0lB = 0, h1lB = 0, h0rB = 0, h1rB = 0;
        #pragma unroll
        for (int nt = 0; nt < 4; nt++) {
            float pA = acc[mt][nt][0] * alv[nt][0] + acc[mt][nt][1] * alv[nt][1];
            float qA = acc[mt][nt][0] * arv[nt][0] + acc[mt][nt][1] * arv[nt][1];
            float pB = acc[mt][nt][2] * alv[nt][0] + acc[mt][nt][3] * alv[nt][1];
            float qB = acc[mt][nt][2] * arv[nt][0] + acc[mt][nt][3] * arv[nt][1];
            if (nt < 2) { h0lA += pA; h0rA += qA; h0lB += pB; h0rB += qB; }
            else        { h1lA += pA; h1rA += qA; h1lB += pB; h1rB += qB; }
        }
        h0lA = qreduce(h0lA); h1lA = qreduce(h1lA);
        h0rA = qreduce(h0rA); h1rA = qreduce(h1rA);
        h0lB = qreduce(h0lB); h1lB = qreduce(h1lB);
        h0rB = qreduce(h0rB); h1rB = qreduce(h1rB);
        if (t == 0) {
            if (rA < N_NODES) {
                g_el[rA * 8 + 2 * wn] = h0lA;  g_el[rA * 8 + 2 * wn + 1] = h1lA;
                g_er[rA * 8 + 2 * wn] = h0rA;  g_er[rA * 8 + 2 * wn + 1] = h1rA;
            }
            if (rB < N_NODES) {
                g_el[rB * 8 + 2 * wn] = h0lB;  g_el[rB * 8 + 2 * wn + 1] = h1lB;
                g_er[rB * 8 + 2 * wn] = h0rB;  g_er[rB * 8 + 2 * wn + 1] = h1rB;
            }
        }
        #pragma unroll
        for (int nt = 0; nt < 4; nt++) {
            int cc = n0 + nt * 8 + 2 * t;
            if (rA < N_NODES)
                *(__half2*)&feat16[(size_t)rA * 128 + cc] =
                    __floats2half2_rn(acc[mt][nt][0], acc[mt][nt][1]);
            if (rB < N_NODES)
                *(__half2*)&feat16[(size_t)rB * 128 + cc] =
                    __floats2half2_rn(acc[mt][nt][2], acc[mt][nt][3]);
        }
    }
}

__device__ __forceinline__ float leaky(float x) { return x > 0.f ? x : NEG * x; }

// ---------------- fused edge softmax + aggregate + ELU (warp per node) -------
// Latency-bound gather: batch 8 independent edges per iteration (MLP=8).
__global__ void edge128_kernel(const __half* __restrict__ feat16,
                               __half* __restrict__ hout) {
    int node = (blockIdx.x * blockDim.x + threadIdx.x) >> 5;
    int lane = threadIdx.x & 31;
    if (node >= N_NODES) return;
    int beg = g_off[node], end = g_off[node + 1];
    int head = lane >> 2;
    float erh = g_er[node * 8 + head];

    float4 acc = make_float4(0.f, 0.f, 0.f, 0.f);
    float den = 0.f;
    int j = beg;
    for (; j + 8 <= end; j += 8) {
        int s[8];
        #pragma unroll
        for (int q = 0; q < 8; q++) s[q] = g_ssrc[j + q];
        float e[8];
        #pragma unroll
        for (int q = 0; q < 8; q++) e[q] = g_el[s[q] * 8 + head];
        uint2 r[8];
        #pragma unroll
        for (int q = 0; q < 8; q++)
            r[q] = *(const uint2*)(feat16 + (size_t)s[q] * 128 + lane * 4);
        #pragma unroll
        for (int q = 0; q < 8; q++) {
            float w = __expf(leaky(e[q] + erh));
            float2 a01 = __half22float2(*(__half2*)&r[q].x);
            float2 a23 = __half22float2(*(__half2*)&r[q].y);
            acc.x += a01.x * w; acc.y += a01.y * w;
            acc.z += a23.x * w; acc.w += a23.y * w;
            den += w;
        }
    }
    for (; j + 4 <= end; j += 4) {
        int s0 = g_ssrc[j], s1 = g_ssrc[j + 1], s2 = g_ssrc[j + 2], s3 = g_ssrc[j + 3];
        float w0 = __expf(leaky(g_el[s0 * 8 + head] + erh));
        float w1 = __expf(leaky(g_el[s1 * 8 + head] + erh));
        float w2 = __expf(leaky(g_el[s2 * 8 + head] + erh));
        float w3 = __expf(leaky(g_el[s3 * 8 + head] + erh));
        uint2 r0 = *(const uint2*)(feat16 + (size_t)s0 * 128 + lane * 4);
        uint2 r1 = *(const uint2*)(feat16 + (size_t)s1 * 128 + lane * 4);
        uint2 r2 = *(const uint2*)(feat16 + (size_t)s2 * 128 + lane * 4);
        uint2 r3 = *(const uint2*)(feat16 + (size_t)s3 * 128 + lane * 4);
        {
            float2 a01 = __half22float2(*(__half2*)&r0.x);
            float2 a23 = __half22float2(*(__half2*)&r0.y);
            acc.x += a01.x * w0; acc.y += a01.y * w0;
            acc.z += a23.x * w0; acc.w += a23.y * w0;
        }
        {
            float2 a01 = __half22float2(*(__half2*)&r1.x);
            float2 a23 = __half22float2(*(__half2*)&r1.y);
            acc.x += a01.x * w1; acc.y += a01.y * w1;
            acc.z += a23.x * w1; acc.w += a23.y * w1;
        }
        {
            float2 a01 = __half22float2(*(__half2*)&r2.x);
            float2 a23 = __half22float2(*(__half2*)&r2.y);
            acc.x += a01.x * w2; acc.y += a01.y * w2;
            acc.z += a23.x * w2; acc.w += a23.y * w2;
        }
        {
            float2 a01 = __half22float2(*(__half2*)&r3.x);
            float2 a23 = __half22float2(*(__half2*)&r3.y);
            acc.x += a01.x * w3; acc.y += a01.y * w3;
            acc.z += a23.x * w3; acc.w += a23.y * w3;
        }
        den += w0 + w1 + w2 + w3;
    }
    for (; j < end; j++) {
        int s = g_ssrc[j];
        float w = __expf(leaky(g_el[s * 8 + head] + erh));
        uint2 r = *(const uint2*)(feat16 + (size_t)s * 128 + lane * 4);
        float2 a01 = __half22float2(*(__half2*)&r.x);
        float2 a23 = __half22float2(*(__half2*)&r.y);
        acc.x += a01.x * w; acc.y += a01.y * w;
        acc.z += a23.x * w; acc.w += a23.y * w;
        den += w;
    }

    float4 o = make_float4(0.f, 0.f, 0.f, 0.f);
    if (den > 0.f) {
        float inv = 1.f / den;
        o.x = acc.x * inv; o.y = acc.y * inv; o.z = acc.z * inv; o.w = acc.w * inv;
        o.x = o.x > 0.f ? o.x : expm1f(o.x);
        o.y = o.y > 0.f ? o.y : expm1f(o.y);
        o.z = o.z > 0.f ? o.z : expm1f(o.z);
        o.w = o.w > 0.f ? o.w : expm1f(o.w);
    }
    uint2 st;
    *(__half2*)&st.x = __floats2half2_rn(o.x, o.y);
    *(__half2*)&st.y = __floats2half2_rn(o.z, o.w);
    *(uint2*)(hout + (size_t)node * 128 + lane * 4) = st;
}

// ---------------- final layer: GEMM (N,128)@(128,10) + el/er -----------------
__global__ void gemm10_kernel(const __half* __restrict__ hin,
                              const float* __restrict__ W,
                              const float* __restrict__ al,
                              const float* __restrict__ ar) {
    __shared__ float Ws[128 * NCLS];
    int tid = threadIdx.x;
    for (int i = tid; i < 128 * NCLS; i += blockDim.x) Ws[i] = W[i];
    __syncthreads();
    int node = (blockIdx.x * blockDim.x + tid) >> 5;
    int lane = tid & 31;
    if (node >= N_NODES) return;
    uint2 raw = *(const uint2*)&hin[(size_t)node * 128 + lane * 4];
    float2 f01 = __half22float2(*(__half2*)&raw.x);
    float2 f23 = __half22float2(*(__half2*)&raw.y);
    float acc[NCLS];
    int k0 = lane * 4;
    #pragma unroll
    for (int c = 0; c < NCLS; c++)
        acc[c] = f01.x * Ws[k0 * NCLS + c] + f01.y * Ws[(k0 + 1) * NCLS + c]
               + f23.x * Ws[(k0 + 2) * NCLS + c] + f23.y * Ws[(k0 + 3) * NCLS + c];
    #pragma unroll
    for (int c = 0; c < NCLS; c++) {
        #pragma unroll
        for (int d = 16; d >= 1; d >>= 1)
            acc[c] += __shfl_xor_sync(0xffffffffu, acc[c], d);
    }
    if (lane == 0) {
        float e_l = 0.f, e_r = 0.f;
        #pragma unroll
        for (int c = 0; c < NCLS; c++) {
            g_feat5[node * NCLS + c] = acc[c];
            e_l += acc[c] * al[c];
            e_r += acc[c] * ar[c];
        }
        g_el5[node] = e_l;
        g_er5[node] = e_r;
    }
}

__global__ void edge10_kernel(float* __restrict__ out) {
    int node = (blockIdx.x * blockDim.x + threadIdx.x) >> 5;
    int lane = threadIdx.x & 31;
    if (node >= N_NODES) return;
    int beg = g_off[node], end = g_off[node + 1];
    float ern = g_er5[node];
    float acc = 0.f, den = 0.f;
    for (int j = beg; j < end; j++) {
        int s = g_ssrc[j];
        float ex = __expf(leaky(g_el5[s] + ern));
        den += ex;
        if (lane < NCLS) acc += g_feat5[s * NCLS + lane] * ex;
    }
    if (lane < NCLS) out[node * NCLS + lane] = den > 0.f ? acc / den : 0.f;
}

// ---------------- launch -----------------------------------------------------
extern "C" void kernel_launch(void* const* d_in, const int* in_sizes, int n_in,
                              void* d_out, int out_size) {
    const float* h   = (const float*)d_in[0];
    const int*   src = (const int*)d_in[1];
    const int*   dst = (const int*)d_in[2];
    const float* W[5]; const float* al[5]; const float* ar[5];
    for (int i = 0; i < 5; i++) {
        W[i]  = (const float*)d_in[3 + 3 * i];
        al[i] = (const float*)d_in[4 + 3 * i];
        ar[i] = (const float*)d_in[5 + 3 * i];
    }

    __half *feat16, *hA, *hB;
    cudaGetSymbolAddress((void**)&feat16, g_feat16);
    cudaGetSymbolAddress((void**)&hA, g_hA);
    cudaGetSymbolAddress((void**)&hB, g_hB);

    const int smem_g = 2 * 128 * PADH * (int)sizeof(__half);   // 69632
    static bool s_init = false;
    static cudaStream_t s_csr;
    static cudaEvent_t ev_fork, ev_join, ev_done;
    if (!s_init) {
        cudaFuncSetAttribute(gemm_fp16<float>,
                             cudaFuncAttributeMaxDynamicSharedMemorySize, smem_g);
        cudaFuncSetAttribute(gemm_fp16<__half>,
                             cudaFuncAttributeMaxDynamicSharedMemorySize, smem_g);
        cudaStreamCreateWithFlags(&s_csr, cudaStreamNonBlocking);
        cudaEventCreateWithFlags(&ev_fork, cudaEventDisableTiming);
        cudaEventCreateWithFlags(&ev_join, cudaEventDisableTiming);
        cudaEventCreateWithFlags(&ev_done, cudaEventDisableTiming);
        s_init = true;
    }

    // ---- fork: CSR build on side stream, overlapped with W-convert + layer-0 --
    cudaEventRecord(ev_fork, 0);
    cudaStreamWaitEvent(s_csr, ev_fork, 0);
    count_rank_kernel<<<(N_EDGES / 4 + 255) / 256, 256, 0, s_csr>>>(dst);
    scan1_kernel<<<NPART, SCAN_BLK, 0, s_csr>>>();
    scan3_kernel<<<(N_NODES + 255) / 256, 256, 0, s_csr>>>();
    scatter2_kernel<<<(N_EDGES / 4 + 255) / 256, 256, 0, s_csr>>>(src, dst);
    cudaEventRecord(ev_join, s_csr);
    // rezero g_cnt for next replay — off the edge-0 critical path; joined at end
    rezero_kernel<<<(N_NODES + 255) / 256, 256, 0, s_csr>>>();
    cudaEventRecord(ev_done, s_csr);

    const int node_warp_grid = (N_NODES * 32 + 255) / 256;  // warp per node
    const int gemm_grid = (N_NODES + 127) / 128;            // 391

    // W convert (all 4 layers, one launch)
    {
        dim3 g(64, 4);
        wsplit_kernel<<<g, 256>>>(W[0], W[1], W[2], W[3]);
    }

    // layer 0 feature path (independent of CSR)
    gemm_fp16<float><<<gemm_grid, 256, smem_g>>>(h, 0, feat16, al[0], ar[0]);
    cudaStreamWaitEvent(0, ev_join, 0);   // join before first edge kernel
    edge128_kernel<<<node_warp_grid, 256>>>(feat16, hA);

    // layers 1-3
    gemm_fp16<__half><<<gemm_grid, 256, smem_g>>>(hA, 1, feat16, al[1], ar[1]);
    edge128_kernel<<<node_warp_grid, 256>>>(feat16, hB);
    gemm_fp16<__half><<<gemm_grid, 256, smem_g>>>(hB, 2, feat16, al[2], ar[2]);
    edge128_kernel<<<node_warp_grid, 256>>>(feat16, hA);
    gemm_fp16<__half><<<gemm_grid, 256, smem_g>>>(hA, 3, feat16, al[3], ar[3]);
    edge128_kernel<<<node_warp_grid, 256>>>(feat16, hB);

    // final projection + edge softmax over 10-dim class features
    gemm10_kernel<<<node_warp_grid, 256>>>(hB, W[4], al[4], ar[4]);
    cudaStreamWaitEvent(0, ev_done, 0);   // join rezero before last kernel
    edge10_kernel<<<node_warp_grid, 256>>>((float*)d_out);
}